// round 7
// baseline (speedup 1.0000x reference)
#include <cuda_runtime.h>

#define CDIM 3755
#define RDIM 214
#define SDIM 13
#define SCBDIM 30
#define STDIM 6
#define HDIM 64
#define KTOP 20
#define CAP 512
#define NT 256
#define NEGF 3.4e38f

__device__ __forceinline__ unsigned f2key(float x) {
    unsigned u = __float_as_uint(x);
    return (u & 0x80000000u) ? ~u : (u | 0x80000000u);
}
__device__ __forceinline__ float key2f(unsigned k) {
    return __uint_as_float((k & 0x80000000u) ? (k & 0x7FFFFFFFu) : ~k);
}
__device__ __forceinline__ unsigned long long packvi(float v, int j) {
    return ((unsigned long long)f2key(v) << 32) | (unsigned)(0x7FFFFFFF - j);
}

__global__ void __launch_bounds__(NT) rerank_kernel(
    const float* __restrict__ charL, const float* __restrict__ radL,
    const float* __restrict__ structL, const float* __restrict__ scL,
    const float* __restrict__ styL, const int* __restrict__ rmask,
    const int* __restrict__ slab, const int* __restrict__ sclab,
    const float* __restrict__ sig, const float* __restrict__ W1,
    const float* __restrict__ b1, const float* __restrict__ W2,
    const float* __restrict__ b2, const float* __restrict__ rwp,
    float* __restrict__ out)
{
    __shared__ unsigned long long cpack[CAP];
    __shared__ float rps[RDIM];
    __shared__ float w1s[6 * HDIM], b1sh[HDIM], w2sh[HDIM];
    __shared__ float sprob[SDIM], predn[STDIM];
    __shared__ float feat6[KTOP][6];
    __shared__ int tIdx[KTOP];
    __shared__ float tVal[KTOP];
    __shared__ float redm[8], reds[8], redt[8];
    __shared__ unsigned long long red64[8];
    __shared__ unsigned long long s_prev;
    __shared__ float s_max, s_sum, s_shift, s_total, s_b2, s_rw;
    __shared__ int s_ncand, s_spred;

    const int b = blockIdx.x;
    const int tid = threadIdx.x, lane = tid & 31, wid = tid >> 5;

    // ---- stage weights ----
    for (int i = tid; i < 6 * HDIM; i += NT) w1s[i] = W1[i];
    if (tid < HDIM) { b1sh[tid] = b1[tid]; w2sh[tid] = W2[tid]; }
    if (tid == 0) { s_b2 = b2[0]; s_rw = rwp[0]; }

    // ---- pass 1: global -> out copy, max, unshifted expsum (row stays L1-hot) ----
    const float* row = charL + (size_t)b * CDIM;
    float* orow = out + (size_t)b * CDIM;
    const int h = (4 - (int)(((size_t)row >> 2) & 3)) & 3;
    const int nv = (CDIM - h) >> 2;
    const int tl = CDIM - h - 4 * nv;
    const float4* r4 = (const float4*)(row + h);
    const bool ast = ((((size_t)(orow + h)) & 15) == 0);
    float4* o4 = (float4*)(orow + h);

    float mx = -NEGF, se = 0.f;
    if (tid < h) {
        float v = row[tid]; orow[tid] = v;
        mx = fmaxf(mx, v); se += __expf(v);
    }
    #pragma unroll
    for (int u = 0; u < 4; u++) {
        int i = tid + u * NT;
        if (i < nv) {
            float4 w = r4[i];
            if (ast) o4[i] = w;
            else {
                int j = h + 4 * i;
                orow[j] = w.x; orow[j + 1] = w.y; orow[j + 2] = w.z; orow[j + 3] = w.w;
            }
            mx = fmaxf(mx, fmaxf(fmaxf(w.x, w.y), fmaxf(w.z, w.w)));
            se += __expf(w.x) + __expf(w.y) + __expf(w.z) + __expf(w.w);
        }
    }
    if (tid < tl) {
        int j = h + 4 * nv + tid;
        float v = row[j]; orow[j] = v;
        mx = fmaxf(mx, v); se += __expf(v);
    }
    float tp = 0.f;
    if (tid < RDIM) {
        float p = 1.f / (1.f + __expf(-radL[(size_t)b * RDIM + tid]));
        rps[tid] = p; tp = p;
    }
    #pragma unroll
    for (int o = 16; o; o >>= 1) {
        mx = fmaxf(mx, __shfl_xor_sync(~0u, mx, o));
        se += __shfl_xor_sync(~0u, se, o);
        tp += __shfl_xor_sync(~0u, tp, o);
    }
    if (lane == 0) { redm[wid] = mx; reds[wid] = se; redt[wid] = tp; }

    // side tasks on distinct warps
    if (tid == 33) {
        const float* st = structL + (size_t)b * SDIM;
        float m = st[0]; float e[SDIM];
        for (int i = 1; i < SDIM; i++) m = fmaxf(m, st[i]);
        float s = 0.f;
        for (int i = 0; i < SDIM; i++) { e[i] = __expf(st[i] - m); s += e[i]; }
        float inv = 1.f / s;
        for (int i = 0; i < SDIM; i++) sprob[i] = e[i] * inv;
    }
    if (tid == 65) {
        const float* sc = scL + (size_t)b * SCBDIM;
        float m = sc[0]; int mi = 0;
        for (int i = 1; i < SCBDIM; i++) { float vv = sc[i]; if (vv > m) { m = vv; mi = i; } }
        s_spred = mi;
    }
    if (tid == 97) {
        const float* sy = styL + (size_t)b * STDIM;
        float vv[STDIM]; float n2 = 0.f;
        for (int i = 0; i < STDIM; i++) { vv[i] = sy[i]; n2 += vv[i] * vv[i]; }
        float n = fmaxf(sqrtf(n2), 1e-12f);
        for (int i = 0; i < STDIM; i++) predn[i] = vv[i] / n;
    }
    __syncthreads();
    if (tid == 0) {
        float m = redm[0], ss = reds[0], tt = redt[0];
        for (int w = 1; w < 8; w++) { m = fmaxf(m, redm[w]); ss += reds[w]; tt += redt[w]; }
        s_max = m; s_sum = ss; s_total = tt;
        s_shift = (m > 60.f) ? m : 0.f;
    }
    __syncthreads();
    if (s_shift != 0.f) {   // overflow-guard; never taken for sane logits
        const float shv = s_shift;
        float se2 = 0.f;
        for (int j = tid; j < CDIM; j += NT) se2 += __expf(row[j] - shv);
        #pragma unroll
        for (int o = 16; o; o >>= 1) se2 += __shfl_xor_sync(~0u, se2, o);
        if (lane == 0) reds[wid] = se2;
        __syncthreads();
        if (tid == 0) { float ss = 0.f; for (int w = 0; w < 8; w++) ss += reds[w]; s_sum = ss; }
        __syncthreads();
    }
    const float rowmax = s_max;

    // ---- collect candidates: LDG.128 (L1-hot) + warp-scan compaction ----
    float dlt = 1.2f;
    int nc;
    for (;;) {
        if (tid == 0) s_ncand = 0;
        __syncthreads();
        const float t = rowmax - dlt;
        #pragma unroll
        for (int u = 0; u < 5; u++) {
            float4 w; int j0; int c;
            if (u < 4) {
                int i = tid + u * NT;
                if (i < nv) { w = r4[i]; j0 = h + 4 * i; }
                else { w.x = w.y = w.z = w.w = -NEGF; j0 = 0; }
                c = (w.x >= t) + (w.y >= t) + (w.z >= t) + (w.w >= t);
            } else {
                // head (tid<h) and tail (tid in [32, 32+tl))
                if (tid < h) { w.x = row[tid]; j0 = tid; }
                else if (tid >= 32 && tid - 32 < tl) { j0 = h + 4 * nv + tid - 32; w.x = row[j0]; }
                else { w.x = -NEGF; j0 = 0; }
                w.y = w.z = w.w = -NEGF;
                c = (w.x >= t);
            }
            int incl = c;
            #pragma unroll
            for (int o = 1; o < 32; o <<= 1) {
                int q = __shfl_up_sync(~0u, incl, o);
                if (lane >= o) incl += q;
            }
            int tot = __shfl_sync(~0u, incl, 31);
            if (tot) {
                int base = 0;
                if (lane == 31) base = atomicAdd(&s_ncand, tot);
                base = __shfl_sync(~0u, base, 31);
                int pos = base + incl - c;
                if (w.x >= t) { if (pos < CAP) cpack[pos] = packvi(w.x, j0); pos++; }
                if (w.y >= t) { if (pos < CAP) cpack[pos] = packvi(w.y, j0 + 1); pos++; }
                if (w.z >= t) { if (pos < CAP) cpack[pos] = packvi(w.z, j0 + 2); pos++; }
                if (w.w >= t) { if (pos < CAP) cpack[pos] = packvi(w.w, j0 + 3); }
            }
        }
        __syncthreads();
        nc = s_ncand;
        if (nc >= KTOP) break;
        dlt *= 1.6f;
        __syncthreads();
    }

    // ---- selection: parallel rank (ties: lower index wins, encoded in pack) ----
    if (nc <= NT) {
        unsigned long long p0 = (tid < nc) ? cpack[tid] : 0ull;
        int r0 = 0;
        #pragma unroll 4
        for (int j = 0; j < nc; j++) r0 += (cpack[j] > p0);
        if (tid < nc && r0 < KTOP) {
            tIdx[r0] = 0x7FFFFFFF - (int)(p0 & 0xFFFFFFFFu);
            tVal[r0] = key2f((unsigned)(p0 >> 32));
        }
    } else if (nc <= CAP) {
        unsigned long long p0 = cpack[tid];
        unsigned long long p1 = (tid + NT < nc) ? cpack[tid + NT] : 0ull;
        int r0 = 0, r1 = 0;
        for (int j = 0; j < nc; j++) {
            unsigned long long q = cpack[j];
            r0 += (q > p0); r1 += (q > p1);
        }
        if (r0 < KTOP) {
            tIdx[r0] = 0x7FFFFFFF - (int)(p0 & 0xFFFFFFFFu);
            tVal[r0] = key2f((unsigned)(p0 >> 32));
        }
        if (tid + NT < nc && r1 < KTOP) {
            tIdx[r1] = 0x7FFFFFFF - (int)(p1 & 0xFFFFFFFFu);
            tVal[r1] = key2f((unsigned)(p1 >> 32));
        }
    } else {
        // robust fallback (adversarial only): 20 rounds of block argmax over global
        unsigned long long prev = ~0ull;
        for (int k = 0; k < KTOP; k++) {
            unsigned long long best = 0ull;
            for (int j = tid; j < CDIM; j += NT) {
                unsigned long long p = packvi(row[j], j);
                if (p < prev && p > best) best = p;
            }
            #pragma unroll
            for (int o = 16; o; o >>= 1) {
                unsigned long long q = __shfl_xor_sync(~0u, best, o);
                if (q > best) best = q;
            }
            if (lane == 0) red64[wid] = best;
            __syncthreads();
            if (tid == 0) {
                unsigned long long m = red64[0];
                for (int w = 1; w < 8; w++) if (red64[w] > m) m = red64[w];
                tIdx[k] = 0x7FFFFFFF - (int)(m & 0xFFFFFFFFu);
                tVal[k] = key2f((unsigned)(m >> 32));
                s_prev = m;
            }
            __syncthreads();
            prev = s_prev;
        }
    }
    __syncthreads();

    // ---- features: 8-lane groups for radical dot; threads 160.. do scalars ----
    const int g = tid >> 3, gl = tid & 7;
    const float total = s_total;
    if (g < KTOP) {
        int c = tIdx[g];
        const int2* m2 = (const int2*)(rmask + (size_t)c * RDIM);
        float det = 0.f; int cnt = 0;
        for (int r = gl; r < RDIM / 2; r += 8) {
            int2 mm = m2[r];
            det = fmaf((float)mm.x, rps[2 * r], det);
            det = fmaf((float)mm.y, rps[2 * r + 1], det);
            cnt += mm.x + mm.y;
        }
        #pragma unroll
        for (int o = 4; o; o >>= 1) {
            det += __shfl_xor_sync(~0u, det, o);
            cnt += __shfl_xor_sync(~0u, cnt, o);
        }
        if (gl == 0) {
            feat6[g][0] = det / fmaxf((float)cnt, 1.f);
            feat6[g][1] = (total - det) / fmaxf(total, 1e-6f);
        }
    }
    if (tid >= 160 && tid < 160 + KTOP) {
        int k = tid - 160;
        int c = tIdx[k];
        feat6[k][2] = sprob[slab[c]];
        feat6[k][3] = fabsf((float)(s_spred - sclab[c])) * (1.f / 29.f);
        const float* s6 = sig + (size_t)c * STDIM;
        float n2 = 0.f, dd = 0.f;
        #pragma unroll
        for (int i = 0; i < STDIM; i++) {
            float vv = s6[i];
            n2 += vv * vv;
            dd += predn[i] * vv;
        }
        float nrm = sqrtf(n2);
        feat6[k][4] = (nrm > 1e-6f) ? dd / fmaxf(nrm, 1e-12f) : 0.f;
        feat6[k][5] = __expf(tVal[k] - s_shift) / s_sum;
    }
    __syncthreads();

    // ---- MLP 6->64->1 (8-lane group per candidate) + direct global scatter ----
    if (g < KTOP) {
        float f0 = feat6[g][0], f1 = feat6[g][1], f2 = feat6[g][2];
        float f3 = feat6[g][3], f4 = feat6[g][4], f5 = feat6[g][5];
        float score = 0.f;
        #pragma unroll
        for (int u = 0; u < 8; u++) {
            int j = gl + u * 8;
            float hh = b1sh[j] + f0 * w1s[j] + f1 * w1s[HDIM + j]
                     + f2 * w1s[2 * HDIM + j] + f3 * w1s[3 * HDIM + j]
                     + f4 * w1s[4 * HDIM + j] + f5 * w1s[5 * HDIM + j];
            score += fmaxf(hh, 0.f) * w2sh[j];
        }
        #pragma unroll
        for (int o = 4; o; o >>= 1) score += __shfl_xor_sync(~0u, score, o);
        // ordered after the pass-1 copy by the intervening __syncthreads
        if (gl == 0) orow[tIdx[g]] = tVal[g] + s_rw * (score + s_b2);
    }
}

extern "C" void kernel_launch(void* const* d_in, const int* in_sizes, int n_in,
                              void* d_out, int out_size) {
    (void)n_in; (void)out_size;
    int Bn = in_sizes[0] / CDIM;
    rerank_kernel<<<Bn, NT>>>(
        (const float*)d_in[0],  (const float*)d_in[1],  (const float*)d_in[2],
        (const float*)d_in[3],  (const float*)d_in[4],  (const int*)d_in[5],
        (const int*)d_in[6],    (const int*)d_in[7],    (const float*)d_in[8],
        (const float*)d_in[9],  (const float*)d_in[10], (const float*)d_in[11],
        (const float*)d_in[12], (const float*)d_in[13], (float*)d_out);
}

// round 8
// speedup vs baseline: 1.2659x; 1.2659x over previous
#include <cuda_runtime.h>

#define CDIM 3755
#define RDIM 214
#define SDIM 13
#define SCBDIM 30
#define STDIM 6
#define HDIM 64
#define KTOP 20
#define CAP 512
#define NT 256
#define NEGF 3.4e38f
#define THR0 2.2f

__device__ __forceinline__ unsigned f2key(float x) {
    unsigned u = __float_as_uint(x);
    return (u & 0x80000000u) ? ~u : (u | 0x80000000u);
}
__device__ __forceinline__ float key2f(unsigned k) {
    return __uint_as_float((k & 0x80000000u) ? (k & 0x7FFFFFFFu) : ~k);
}
__device__ __forceinline__ unsigned long long packvi(float v, int j) {
    return ((unsigned long long)f2key(v) << 32) | (unsigned)(0x7FFFFFFF - j);
}

__global__ void __launch_bounds__(NT) rerank_kernel(
    const float* __restrict__ charL, const float* __restrict__ radL,
    const float* __restrict__ structL, const float* __restrict__ scL,
    const float* __restrict__ styL, const int* __restrict__ rmask,
    const int* __restrict__ slab, const int* __restrict__ sclab,
    const float* __restrict__ sig, const float* __restrict__ W1,
    const float* __restrict__ b1, const float* __restrict__ W2,
    const float* __restrict__ b2, const float* __restrict__ rwp,
    float* __restrict__ out)
{
    __shared__ unsigned long long cpack[CAP];
    __shared__ float rps[RDIM];
    __shared__ float w1s[6 * HDIM], b1sh[HDIM], w2sh[HDIM];
    __shared__ float sprob[SDIM], predn[STDIM];
    __shared__ float feat6[KTOP][6];
    __shared__ int tIdx[KTOP];
    __shared__ float tVal[KTOP];
    __shared__ float reds[8], redt[8], redm[8];
    __shared__ unsigned long long red64[8];
    __shared__ unsigned long long s_prev;
    __shared__ float s_sum, s_shift, s_total, s_b2, s_rw;
    __shared__ int s_ncand, s_spred;

    const int b = blockIdx.x;
    const int tid = threadIdx.x, lane = tid & 31, wid = tid >> 5;
    const unsigned lm = (1u << lane) - 1u;

    // ---- stage weights + init ----
    for (int i = tid; i < 6 * HDIM; i += NT) w1s[i] = W1[i];
    if (tid < HDIM) { b1sh[tid] = b1[tid]; w2sh[tid] = W2[tid]; }
    if (tid == 0) { s_b2 = b2[0]; s_rw = rwp[0]; s_ncand = 0; s_shift = 0.f; }
    __syncthreads();

    // ---- pass 1 (fused): copy to out + unshifted expsum + fixed-threshold collect ----
    const float* row = charL + (size_t)b * CDIM;
    float* orow = out + (size_t)b * CDIM;
    const int h = (4 - (int)(((size_t)row >> 2) & 3)) & 3;
    const int nv = (CDIM - h) >> 2;
    const int tl = CDIM - h - 4 * nv;
    const float4* r4 = (const float4*)(row + h);
    const bool ast = ((((size_t)(orow + h)) & 15) == 0);
    float4* o4 = (float4*)(orow + h);

    float se = 0.f;
    const float t0 = THR0;
    #pragma unroll
    for (int u = 0; u < 4; u++) {
        int i = tid + u * NT;
        float4 w;
        bool act = i < nv;
        if (act) {
            w = r4[i];
            if (ast) o4[i] = w;
            else {
                int j = h + 4 * i;
                orow[j] = w.x; orow[j + 1] = w.y; orow[j + 2] = w.z; orow[j + 3] = w.w;
            }
            se += __expf(w.x) + __expf(w.y) + __expf(w.z) + __expf(w.w);
        } else { w.x = w.y = w.z = w.w = -NEGF; }
        bool c0 = w.x >= t0, c1 = w.y >= t0, c2 = w.z >= t0, c3 = w.w >= t0;
        unsigned m0 = __ballot_sync(~0u, c0), m1 = __ballot_sync(~0u, c1);
        unsigned m2 = __ballot_sync(~0u, c2), m3 = __ballot_sync(~0u, c3);
        int tot = __popc(m0) + __popc(m1) + __popc(m2) + __popc(m3);
        if (tot) {
            int base = 0;
            if (lane == 0) base = atomicAdd(&s_ncand, tot);
            base = __shfl_sync(~0u, base, 0);
            int j0 = h + 4 * i;
            int off = 0, pos;
            if (c0) { pos = base + __popc(m0 & lm); if (pos < CAP) cpack[pos] = packvi(w.x, j0); }
            off += __popc(m0);
            if (c1) { pos = base + off + __popc(m1 & lm); if (pos < CAP) cpack[pos] = packvi(w.y, j0 + 1); }
            off += __popc(m1);
            if (c2) { pos = base + off + __popc(m2 & lm); if (pos < CAP) cpack[pos] = packvi(w.z, j0 + 2); }
            off += __popc(m2);
            if (c3) { pos = base + off + __popc(m3 & lm); if (pos < CAP) cpack[pos] = packvi(w.w, j0 + 3); }
        }
    }
    // head (warp 0) and tail (warp 1) scalars
    if (wid == 0) {
        float v = -NEGF;
        if (lane < h) { v = row[lane]; orow[lane] = v; se += __expf(v); }
        bool c = v >= t0;
        unsigned m = __ballot_sync(~0u, c);
        if (m) {
            int base = 0;
            if (lane == __ffs(m) - 1) base = atomicAdd(&s_ncand, __popc(m));
            base = __shfl_sync(~0u, base, __ffs(m) - 1);
            if (c) { int pos = base + __popc(m & lm); if (pos < CAP) cpack[pos] = packvi(v, lane); }
        }
    }
    if (wid == 1) {
        float v = -NEGF;
        int j = h + 4 * nv + lane;
        if (lane < tl) { v = row[j]; orow[j] = v; se += __expf(v); }
        bool c = v >= t0;
        unsigned m = __ballot_sync(~0u, c);
        if (m) {
            int base = 0;
            if (lane == __ffs(m) - 1) base = atomicAdd(&s_ncand, __popc(m));
            base = __shfl_sync(~0u, base, __ffs(m) - 1);
            if (c) { int pos = base + __popc(m & lm); if (pos < CAP) cpack[pos] = packvi(v, j); }
        }
    }

    float tp = 0.f;
    if (tid < RDIM) {
        float p = 1.f / (1.f + __expf(-radL[(size_t)b * RDIM + tid]));
        rps[tid] = p; tp = p;
    }
    #pragma unroll
    for (int o = 16; o; o >>= 1) {
        se += __shfl_xor_sync(~0u, se, o);
        tp += __shfl_xor_sync(~0u, tp, o);
    }
    if (lane == 0) { reds[wid] = se; redt[wid] = tp; }

    // side tasks on distinct warps
    if (tid == 33) {
        const float* st = structL + (size_t)b * SDIM;
        float m = st[0]; float e[SDIM];
        for (int i = 1; i < SDIM; i++) m = fmaxf(m, st[i]);
        float s = 0.f;
        for (int i = 0; i < SDIM; i++) { e[i] = __expf(st[i] - m); s += e[i]; }
        float inv = 1.f / s;
        for (int i = 0; i < SDIM; i++) sprob[i] = e[i] * inv;
    }
    if (tid == 65) {
        const float* sc = scL + (size_t)b * SCBDIM;
        float m = sc[0]; int mi = 0;
        for (int i = 1; i < SCBDIM; i++) { float vv = sc[i]; if (vv > m) { m = vv; mi = i; } }
        s_spred = mi;
    }
    if (tid == 97) {
        const float* sy = styL + (size_t)b * STDIM;
        float vv[STDIM]; float n2 = 0.f;
        for (int i = 0; i < STDIM; i++) { vv[i] = sy[i]; n2 += vv[i] * vv[i]; }
        float n = fmaxf(sqrtf(n2), 1e-12f);
        for (int i = 0; i < STDIM; i++) predn[i] = vv[i] / n;
    }
    __syncthreads();
    if (tid == 0) {
        float ss = 0.f, tt = 0.f;
        for (int w = 0; w < 8; w++) { ss += reds[w]; tt += redt[w]; }
        s_sum = ss; s_total = tt;
    }
    __syncthreads();

    // ---- guard: expsum overflow/underflow (never taken for sane logits) ----
    if (isinf(s_sum) || isnan(s_sum) || s_sum < 1e-30f) {
        float mx = -NEGF;
        for (int j = tid; j < CDIM; j += NT) mx = fmaxf(mx, row[j]);
        #pragma unroll
        for (int o = 16; o; o >>= 1) mx = fmaxf(mx, __shfl_xor_sync(~0u, mx, o));
        if (lane == 0) redm[wid] = mx;
        __syncthreads();
        if (tid == 0) {
            float m = redm[0];
            for (int w = 1; w < 8; w++) m = fmaxf(m, redm[w]);
            s_shift = m;
        }
        __syncthreads();
        float se2 = 0.f;
        const float shv = s_shift;
        for (int j = tid; j < CDIM; j += NT) se2 += __expf(row[j] - shv);
        #pragma unroll
        for (int o = 16; o; o >>= 1) se2 += __shfl_xor_sync(~0u, se2, o);
        if (lane == 0) reds[wid] = se2;
        __syncthreads();
        if (tid == 0) { float ss = 0.f; for (int w = 0; w < 8; w++) ss += reds[w]; s_sum = ss; }
        __syncthreads();
    }

    // ---- retry with lower threshold (rare) ----
    int nc = s_ncand;
    float t = t0;
    while (nc < KTOP) {
        __syncthreads();
        if (tid == 0) s_ncand = 0;
        t -= 1.5f;
        __syncthreads();
        for (int base_j = 0; base_j < CDIM; base_j += NT) {
            int j = base_j + tid;
            float v = (j < CDIM) ? row[j] : -NEGF;
            bool c = v >= t;
            unsigned m = __ballot_sync(~0u, c);
            if (m) {
                int base = 0;
                if (lane == __ffs(m) - 1) base = atomicAdd(&s_ncand, __popc(m));
                base = __shfl_sync(~0u, base, __ffs(m) - 1);
                if (c) { int pos = base + __popc(m & lm); if (pos < CAP) cpack[pos] = packvi(v, j); }
            }
        }
        __syncthreads();
        nc = s_ncand;
    }

    // ---- selection: parallel rank (ties: lower index wins, encoded in pack) ----
    if (nc <= NT) {
        if (tid - lane < nc) {   // whole-warp guard: idle warps skip
            unsigned long long p0 = (tid < nc) ? cpack[tid] : 0ull;
            int r0 = 0;
            #pragma unroll 4
            for (int j = 0; j < nc; j++) r0 += (cpack[j] > p0);
            if (tid < nc && r0 < KTOP) {
                tIdx[r0] = 0x7FFFFFFF - (int)(p0 & 0xFFFFFFFFu);
                tVal[r0] = key2f((unsigned)(p0 >> 32));
            }
        }
    } else if (nc <= CAP) {
        unsigned long long p0 = cpack[tid];
        unsigned long long p1 = (tid + NT < nc) ? cpack[tid + NT] : 0ull;
        int r0 = 0, r1 = 0;
        for (int j = 0; j < nc; j++) {
            unsigned long long q = cpack[j];
            r0 += (q > p0); r1 += (q > p1);
        }
        if (r0 < KTOP) {
            tIdx[r0] = 0x7FFFFFFF - (int)(p0 & 0xFFFFFFFFu);
            tVal[r0] = key2f((unsigned)(p0 >> 32));
        }
        if (tid + NT < nc && r1 < KTOP) {
            tIdx[r1] = 0x7FFFFFFF - (int)(p1 & 0xFFFFFFFFu);
            tVal[r1] = key2f((unsigned)(p1 >> 32));
        }
    } else {
        // robust fallback (adversarial only): 20 rounds of block argmax over global
        unsigned long long prev = ~0ull;
        for (int k = 0; k < KTOP; k++) {
            unsigned long long best = 0ull;
            for (int j = tid; j < CDIM; j += NT) {
                unsigned long long p = packvi(row[j], j);
                if (p < prev && p > best) best = p;
            }
            #pragma unroll
            for (int o = 16; o; o >>= 1) {
                unsigned long long q = __shfl_xor_sync(~0u, best, o);
                if (q > best) best = q;
            }
            if (lane == 0) red64[wid] = best;
            __syncthreads();
            if (tid == 0) {
                unsigned long long m = red64[0];
                for (int w = 1; w < 8; w++) if (red64[w] > m) m = red64[w];
                tIdx[k] = 0x7FFFFFFF - (int)(m & 0xFFFFFFFFu);
                tVal[k] = key2f((unsigned)(m >> 32));
                s_prev = m;
            }
            __syncthreads();
            prev = s_prev;
        }
    }
    __syncthreads();

    // ---- features: 8-lane groups for radical dot; threads 160.. do scalars ----
    const int g = tid >> 3, gl = tid & 7;
    const float total = s_total;
    if (g < KTOP) {
        int c = tIdx[g];
        const int2* m2 = (const int2*)(rmask + (size_t)c * RDIM);
        float det = 0.f; int cnt = 0;
        for (int r = gl; r < RDIM / 2; r += 8) {
            int2 mm = m2[r];
            det = fmaf((float)mm.x, rps[2 * r], det);
            det = fmaf((float)mm.y, rps[2 * r + 1], det);
            cnt += mm.x + mm.y;
        }
        #pragma unroll
        for (int o = 4; o; o >>= 1) {
            det += __shfl_xor_sync(~0u, det, o);
            cnt += __shfl_xor_sync(~0u, cnt, o);
        }
        if (gl == 0) {
            feat6[g][0] = det / fmaxf((float)cnt, 1.f);
            feat6[g][1] = (total - det) / fmaxf(total, 1e-6f);
        }
    }
    if (tid >= 160 && tid < 160 + KTOP) {
        int k = tid - 160;
        int c = tIdx[k];
        feat6[k][2] = sprob[slab[c]];
        feat6[k][3] = fabsf((float)(s_spred - sclab[c])) * (1.f / 29.f);
        const float* s6 = sig + (size_t)c * STDIM;
        float n2 = 0.f, dd = 0.f;
        #pragma unroll
        for (int i = 0; i < STDIM; i++) {
            float vv = s6[i];
            n2 += vv * vv;
            dd += predn[i] * vv;
        }
        float nrm = sqrtf(n2);
        feat6[k][4] = (nrm > 1e-6f) ? dd / fmaxf(nrm, 1e-12f) : 0.f;
        feat6[k][5] = __expf(tVal[k] - s_shift) / s_sum;
    }
    __syncthreads();

    // ---- MLP 6->64->1 (8-lane group per candidate) + direct global scatter ----
    if (g < KTOP) {
        float f0 = feat6[g][0], f1 = feat6[g][1], f2 = feat6[g][2];
        float f3 = feat6[g][3], f4 = feat6[g][4], f5 = feat6[g][5];
        float score = 0.f;
        #pragma unroll
        for (int u = 0; u < 8; u++) {
            int j = gl + u * 8;
            float hh = b1sh[j] + f0 * w1s[j] + f1 * w1s[HDIM + j]
                     + f2 * w1s[2 * HDIM + j] + f3 * w1s[3 * HDIM + j]
                     + f4 * w1s[4 * HDIM + j] + f5 * w1s[5 * HDIM + j];
            score += fmaxf(hh, 0.f) * w2sh[j];
        }
        #pragma unroll
        for (int o = 4; o; o >>= 1) score += __shfl_xor_sync(~0u, score, o);
        // ordered after the pass-1 copy by the intervening __syncthreads
        if (gl == 0) orow[tIdx[g]] = tVal[g] + s_rw * (score + s_b2);
    }
}

extern "C" void kernel_launch(void* const* d_in, const int* in_sizes, int n_in,
                              void* d_out, int out_size) {
    (void)n_in; (void)out_size;
    int Bn = in_sizes[0] / CDIM;
    rerank_kernel<<<Bn, NT>>>(
        (const float*)d_in[0],  (const float*)d_in[1],  (const float*)d_in[2],
        (const float*)d_in[3],  (const float*)d_in[4],  (const int*)d_in[5],
        (const int*)d_in[6],    (const int*)d_in[7],    (const float*)d_in[8],
        (const float*)d_in[9],  (const float*)d_in[10], (const float*)d_in[11],
        (const float*)d_in[12], (const float*)d_in[13], (float*)d_out);
}

// round 9
// speedup vs baseline: 1.6226x; 1.2818x over previous
#include <cuda_runtime.h>

#define CDIM 3755
#define NV 938              // (CDIM - h) >> 2 == 938 for every h in 0..3
#define RDIM 214
#define SDIM 13
#define SCBDIM 30
#define STDIM 6
#define HDIM 64
#define KTOP 20
#define CAP 512
#define NT 256
#define NEGF 3.4e38f
#define THR0 2.2f

__device__ __forceinline__ unsigned f2key(float x) {
    unsigned u = __float_as_uint(x);
    return (u & 0x80000000u) ? ~u : (u | 0x80000000u);
}
__device__ __forceinline__ float key2f(unsigned k) {
    return __uint_as_float((k & 0x80000000u) ? (k & 0x7FFFFFFFu) : ~k);
}
__device__ __forceinline__ unsigned long long packvi(float v, int j) {
    return ((unsigned long long)f2key(v) << 32) | (unsigned)(0x7FFFFFFF - j);
}
__device__ __forceinline__ unsigned su32(const void* p) {
    unsigned a;
    asm("{ .reg .u64 t; cvta.to.shared.u64 t, %1; cvt.u32.u64 %0, t; }" : "=r"(a) : "l"(p));
    return a;
}

__global__ void __launch_bounds__(NT) rerank_kernel(
    const float* __restrict__ charL, const float* __restrict__ radL,
    const float* __restrict__ structL, const float* __restrict__ scL,
    const float* __restrict__ styL, const int* __restrict__ rmask,
    const int* __restrict__ slab, const int* __restrict__ sclab,
    const float* __restrict__ sig, const float* __restrict__ W1,
    const float* __restrict__ b1, const float* __restrict__ W2,
    const float* __restrict__ b2, const float* __restrict__ rwp,
    float* __restrict__ out)
{
    __shared__ __align__(128) float4 srow4[NV];     // TMA-loaded middle of the row
    __shared__ float shHT[8];                        // head [0..3], tail [4..7]
    __shared__ __align__(8) unsigned long long s_mbar;
    __shared__ unsigned long long cpack[CAP];
    __shared__ float rps[RDIM];
    __shared__ float w1s[6 * HDIM], b1sh[HDIM], w2sh[HDIM];
    __shared__ float sprob[SDIM], predn[STDIM];
    __shared__ float feat6[KTOP][6];
    __shared__ int tIdx[KTOP];
    __shared__ float tVal[KTOP];
    __shared__ float reds[8], redt[8], redm[8];
    __shared__ unsigned long long red64[8];
    __shared__ unsigned long long s_prev;
    __shared__ float s_sum, s_shift, s_total, s_b2, s_rw;
    __shared__ int s_ncand, s_spred;

    float* srow = (float*)srow4;
    const int b = blockIdx.x;
    const int tid = threadIdx.x, lane = tid & 31, wid = tid >> 5;
    const unsigned lm = (1u << lane) - 1u;

    const float* row = charL + (size_t)b * CDIM;
    float* orow = out + (size_t)b * CDIM;
    const int h = (4 - (int)(((size_t)row >> 2) & 3)) & 3;
    const int tl = 3 - h;
    const int ho = (4 - (int)(((size_t)orow >> 2) & 3)) & 3;

    // ---- init: weights + mbarrier ----
    for (int i = tid; i < 6 * HDIM; i += NT) w1s[i] = W1[i];
    if (tid < HDIM) { b1sh[tid] = b1[tid]; w2sh[tid] = W2[tid]; }
    if (tid == 0) {
        s_b2 = b2[0]; s_rw = rwp[0]; s_ncand = 0; s_shift = 0.f;
        asm volatile("mbarrier.init.shared.b64 [%0], 1;" :: "r"(su32(&s_mbar)) : "memory");
    }
    __syncthreads();

    // ---- issue TMA bulk load of the aligned middle (overlaps side tasks) ----
    if (tid == 0) {
        unsigned mb = su32(&s_mbar);
        asm volatile("mbarrier.arrive.expect_tx.shared.b64 _, [%0], %1;"
                     :: "r"(mb), "r"(NV * 16) : "memory");
        asm volatile("cp.async.bulk.shared::cta.global.mbarrier::complete_tx::bytes "
                     "[%0], [%1], %2, [%3];"
                     :: "r"(su32(srow4)), "l"(row + h), "r"(NV * 16), "r"(mb) : "memory");
    }

    // ---- head/tail scalars: load + copy-out + stash in smem ----
    float seHT = 0.f;
    if (wid == 0 && lane < h) {
        float v = row[lane]; shHT[lane] = v; orow[lane] = v; seHT = __expf(v);
    }
    if (wid == 1 && lane < tl) {
        int j = h + 4 * NV + lane;
        float v = row[j]; shHT[4 + lane] = v; orow[j] = v; seHT = __expf(v);
    }

    // ---- radical sigmoid + total (global loads overlap TMA flight) ----
    float tp = 0.f;
    if (tid < RDIM) {
        float p = 1.f / (1.f + __expf(-radL[(size_t)b * RDIM + tid]));
        rps[tid] = p; tp = p;
    }
    // side tasks on distinct warps
    if (tid == 65) {
        const float* st = structL + (size_t)b * SDIM;
        float m = st[0]; float e[SDIM];
        for (int i = 1; i < SDIM; i++) m = fmaxf(m, st[i]);
        float s = 0.f;
        for (int i = 0; i < SDIM; i++) { e[i] = __expf(st[i] - m); s += e[i]; }
        float inv = 1.f / s;
        for (int i = 0; i < SDIM; i++) sprob[i] = e[i] * inv;
    }
    if (tid == 97) {
        const float* sc = scL + (size_t)b * SCBDIM;
        float m = sc[0]; int mi = 0;
        for (int i = 1; i < SCBDIM; i++) { float vv = sc[i]; if (vv > m) { m = vv; mi = i; } }
        s_spred = mi;
    }
    if (tid == 129) {
        const float* sy = styL + (size_t)b * STDIM;
        float vv[STDIM]; float n2 = 0.f;
        for (int i = 0; i < STDIM; i++) { vv[i] = sy[i]; n2 += vv[i] * vv[i]; }
        float n = fmaxf(sqrtf(n2), 1e-12f);
        for (int i = 0; i < STDIM; i++) predn[i] = vv[i] / n;
    }

    // ---- wait for TMA load completion ----
    {
        unsigned mb = su32(&s_mbar);
        unsigned done;
        asm volatile(
            "{\n\t.reg .pred p;\n\t"
            "mbarrier.try_wait.parity.shared.b64 p, [%1], 0;\n\t"
            "selp.b32 %0, 1, 0, p;\n\t}"
            : "=r"(done) : "r"(mb) : "memory");
        while (!done) {
            asm volatile(
                "{\n\t.reg .pred p;\n\t"
                "mbarrier.try_wait.parity.shared.b64 p, [%1], 0;\n\t"
                "selp.b32 %0, 1, 0, p;\n\t}"
                : "=r"(done) : "r"(mb) : "memory");
        }
    }

    // ---- fused sweep over smem: unshifted expsum + fixed-threshold collect ----
    float se = seHT;
    const float t0 = THR0;
    #pragma unroll
    for (int u = 0; u < 4; u++) {
        int i = tid + u * NT;
        float4 w;
        if (i < NV) {
            w = srow4[i];
            se += __expf(w.x) + __expf(w.y) + __expf(w.z) + __expf(w.w);
        } else { w.x = w.y = w.z = w.w = -NEGF; }
        bool c0 = w.x >= t0, c1 = w.y >= t0, c2 = w.z >= t0, c3 = w.w >= t0;
        unsigned m0 = __ballot_sync(~0u, c0), m1 = __ballot_sync(~0u, c1);
        unsigned m2 = __ballot_sync(~0u, c2), m3 = __ballot_sync(~0u, c3);
        int tot = __popc(m0) + __popc(m1) + __popc(m2) + __popc(m3);
        if (tot) {
            int base = 0;
            if (lane == 0) base = atomicAdd(&s_ncand, tot);
            base = __shfl_sync(~0u, base, 0);
            int j0 = h + 4 * i;
            int off = 0, pos;
            if (c0) { pos = base + __popc(m0 & lm); if (pos < CAP) cpack[pos] = packvi(w.x, j0); }
            off += __popc(m0);
            if (c1) { pos = base + off + __popc(m1 & lm); if (pos < CAP) cpack[pos] = packvi(w.y, j0 + 1); }
            off += __popc(m1);
            if (c2) { pos = base + off + __popc(m2 & lm); if (pos < CAP) cpack[pos] = packvi(w.z, j0 + 2); }
            off += __popc(m2);
            if (c3) { pos = base + off + __popc(m3 & lm); if (pos < CAP) cpack[pos] = packvi(w.w, j0 + 3); }
        }
    }
    // head/tail candidates (warps 0/1)
    if (wid < 2) {
        float v = -NEGF; int j = 0;
        if (wid == 0) { if (lane < h) { v = shHT[lane]; j = lane; } }
        else { if (lane < tl) { v = shHT[4 + lane]; j = h + 4 * NV + lane; } }
        bool c = v >= t0;
        unsigned m = __ballot_sync(~0u, c);
        if (m) {
            int ldr = __ffs(m) - 1;
            int base = 0;
            if (lane == ldr) base = atomicAdd(&s_ncand, __popc(m));
            base = __shfl_sync(~0u, base, ldr);
            if (c) { int pos = base + __popc(m & lm); if (pos < CAP) cpack[pos] = packvi(v, j); }
        }
    }
    #pragma unroll
    for (int o = 16; o; o >>= 1) {
        se += __shfl_xor_sync(~0u, se, o);
        tp += __shfl_xor_sync(~0u, tp, o);
    }
    if (lane == 0) { reds[wid] = se; redt[wid] = tp; }
    __syncthreads();
    if (tid == 0) {
        float ss = 0.f, tt = 0.f;
        for (int w = 0; w < 8; w++) { ss += reds[w]; tt += redt[w]; }
        s_sum = ss; s_total = tt;
    }
    __syncthreads();

    // ---- guard: expsum overflow/underflow (never taken for sane logits) ----
    if (isinf(s_sum) || isnan(s_sum) || s_sum < 1e-30f) {
        float mx = -NEGF;
        for (int k = tid; k < 4 * NV; k += NT) mx = fmaxf(mx, srow[k]);
        if (tid < h) mx = fmaxf(mx, shHT[tid]);
        if (tid >= 32 && tid - 32 < tl) mx = fmaxf(mx, shHT[4 + tid - 32]);
        #pragma unroll
        for (int o = 16; o; o >>= 1) mx = fmaxf(mx, __shfl_xor_sync(~0u, mx, o));
        if (lane == 0) redm[wid] = mx;
        __syncthreads();
        if (tid == 0) {
            float m = redm[0];
            for (int w = 1; w < 8; w++) m = fmaxf(m, redm[w]);
            s_shift = m;
        }
        __syncthreads();
        const float shv = s_shift;
        float se2 = 0.f;
        for (int k = tid; k < 4 * NV; k += NT) se2 += __expf(srow[k] - shv);
        if (tid < h) se2 += __expf(shHT[tid] - shv);
        if (tid >= 32 && tid - 32 < tl) se2 += __expf(shHT[4 + tid - 32] - shv);
        #pragma unroll
        for (int o = 16; o; o >>= 1) se2 += __shfl_xor_sync(~0u, se2, o);
        if (lane == 0) reds[wid] = se2;
        __syncthreads();
        if (tid == 0) { float ss = 0.f; for (int w = 0; w < 8; w++) ss += reds[w]; s_sum = ss; }
        __syncthreads();
    }

    // ---- retry with lower threshold (rare) ----
    int nc = s_ncand;
    float t = t0;
    while (nc < KTOP) {
        __syncthreads();
        if (tid == 0) s_ncand = 0;
        t -= 1.5f;
        __syncthreads();
        for (int base_k = 0; base_k < 4 * NV; base_k += NT) {
            int k = base_k + tid;
            float v = (k < 4 * NV) ? srow[k] : -NEGF;
            bool c = v >= t;
            unsigned m = __ballot_sync(~0u, c);
            if (m) {
                int ldr = __ffs(m) - 1;
                int base = 0;
                if (lane == ldr) base = atomicAdd(&s_ncand, __popc(m));
                base = __shfl_sync(~0u, base, ldr);
                if (c) { int pos = base + __popc(m & lm); if (pos < CAP) cpack[pos] = packvi(v, h + k); }
            }
        }
        if (wid < 2) {
            float v = -NEGF; int j = 0;
            if (wid == 0) { if (lane < h) { v = shHT[lane]; j = lane; } }
            else { if (lane < tl) { v = shHT[4 + lane]; j = h + 4 * NV + lane; } }
            bool c = v >= t;
            unsigned m = __ballot_sync(~0u, c);
            if (m) {
                int ldr = __ffs(m) - 1;
                int base = 0;
                if (lane == ldr) base = atomicAdd(&s_ncand, __popc(m));
                base = __shfl_sync(~0u, base, ldr);
                if (c) { int pos = base + __popc(m & lm); if (pos < CAP) cpack[pos] = packvi(v, j); }
            }
        }
        __syncthreads();
        nc = s_ncand;
    }

    // ---- selection: parallel rank (ties: lower index wins, encoded in pack) ----
    if (nc <= NT) {
        if (tid - lane < nc) {
            unsigned long long p0 = (tid < nc) ? cpack[tid] : 0ull;
            int r0 = 0;
            #pragma unroll 4
            for (int j = 0; j < nc; j++) r0 += (cpack[j] > p0);
            if (tid < nc && r0 < KTOP) {
                tIdx[r0] = 0x7FFFFFFF - (int)(p0 & 0xFFFFFFFFu);
                tVal[r0] = key2f((unsigned)(p0 >> 32));
            }
        }
    } else if (nc <= CAP) {
        unsigned long long p0 = cpack[tid];
        unsigned long long p1 = (tid + NT < nc) ? cpack[tid + NT] : 0ull;
        int r0 = 0, r1 = 0;
        for (int j = 0; j < nc; j++) {
            unsigned long long q = cpack[j];
            r0 += (q > p0); r1 += (q > p1);
        }
        if (r0 < KTOP) {
            tIdx[r0] = 0x7FFFFFFF - (int)(p0 & 0xFFFFFFFFu);
            tVal[r0] = key2f((unsigned)(p0 >> 32));
        }
        if (tid + NT < nc && r1 < KTOP) {
            tIdx[r1] = 0x7FFFFFFF - (int)(p1 & 0xFFFFFFFFu);
            tVal[r1] = key2f((unsigned)(p1 >> 32));
        }
    } else {
        // robust fallback (adversarial only): 20 rounds of block argmax over smem
        unsigned long long prev = ~0ull;
        for (int k = 0; k < KTOP; k++) {
            unsigned long long best = 0ull;
            for (int kk = tid; kk < 4 * NV; kk += NT) {
                unsigned long long p = packvi(srow[kk], h + kk);
                if (p < prev && p > best) best = p;
            }
            if (tid < h) { unsigned long long p = packvi(shHT[tid], tid); if (p < prev && p > best) best = p; }
            if (tid >= 32 && tid - 32 < tl) {
                unsigned long long p = packvi(shHT[4 + tid - 32], h + 4 * NV + tid - 32);
                if (p < prev && p > best) best = p;
            }
            #pragma unroll
            for (int o = 16; o; o >>= 1) {
                unsigned long long q = __shfl_xor_sync(~0u, best, o);
                if (q > best) best = q;
            }
            if (lane == 0) red64[wid] = best;
            __syncthreads();
            if (tid == 0) {
                unsigned long long m = red64[0];
                for (int w = 1; w < 8; w++) if (red64[w] > m) m = red64[w];
                tIdx[k] = 0x7FFFFFFF - (int)(m & 0xFFFFFFFFu);
                tVal[k] = key2f((unsigned)(m >> 32));
                s_prev = m;
            }
            __syncthreads();
            prev = s_prev;
        }
    }
    __syncthreads();

    // ---- features: 8-lane groups for radical dot; threads 160.. do scalars ----
    const int g = tid >> 3, gl = tid & 7;
    const float total = s_total;
    if (g < KTOP) {
        int c = tIdx[g];
        const int2* m2 = (const int2*)(rmask + (size_t)c * RDIM);
        float det = 0.f; int cnt = 0;
        for (int r = gl; r < RDIM / 2; r += 8) {
            int2 mm = m2[r];
            det = fmaf((float)mm.x, rps[2 * r], det);
            det = fmaf((float)mm.y, rps[2 * r + 1], det);
            cnt += mm.x + mm.y;
        }
        #pragma unroll
        for (int o = 4; o; o >>= 1) {
            det += __shfl_xor_sync(~0u, det, o);
            cnt += __shfl_xor_sync(~0u, cnt, o);
        }
        if (gl == 0) {
            feat6[g][0] = det / fmaxf((float)cnt, 1.f);
            feat6[g][1] = (total - det) / fmaxf(total, 1e-6f);
        }
    }
    if (tid >= 160 && tid < 160 + KTOP) {
        int k = tid - 160;
        int c = tIdx[k];
        feat6[k][2] = sprob[slab[c]];
        feat6[k][3] = fabsf((float)(s_spred - sclab[c])) * (1.f / 29.f);
        const float* s6 = sig + (size_t)c * STDIM;
        float n2 = 0.f, dd = 0.f;
        #pragma unroll
        for (int i = 0; i < STDIM; i++) {
            float vv = s6[i];
            n2 += vv * vv;
            dd += predn[i] * vv;
        }
        float nrm = sqrtf(n2);
        feat6[k][4] = (nrm > 1e-6f) ? dd / fmaxf(nrm, 1e-12f) : 0.f;
        feat6[k][5] = __expf(tVal[k] - s_shift) / s_sum;
    }
    __syncthreads();

    // ---- MLP 6->64->1; patch scores into smem row (or global for head/tail) ----
    if (g < KTOP) {
        float f0 = feat6[g][0], f1 = feat6[g][1], f2 = feat6[g][2];
        float f3 = feat6[g][3], f4 = feat6[g][4], f5 = feat6[g][5];
        float score = 0.f;
        #pragma unroll
        for (int u = 0; u < 8; u++) {
            int j = gl + u * 8;
            float hh = b1sh[j] + f0 * w1s[j] + f1 * w1s[HDIM + j]
                     + f2 * w1s[2 * HDIM + j] + f3 * w1s[3 * HDIM + j]
                     + f4 * w1s[4 * HDIM + j] + f5 * w1s[5 * HDIM + j];
            score += fmaxf(hh, 0.f) * w2sh[j];
        }
        #pragma unroll
        for (int o = 4; o; o >>= 1) score += __shfl_xor_sync(~0u, score, o);
        if (gl == 0) {
            int idx = tIdx[g];
            float comb = tVal[g] + s_rw * (score + s_b2);
            if (idx >= h && idx < h + 4 * NV) srow[idx - h] = comb;
            else orow[idx] = comb;       // head/tail patch (ordered after copy by barriers)
        }
    }
    __syncthreads();

    // ---- write the middle back: TMA bulk store (or scalar fallback) ----
    if (ho == h) {
        if (tid == 0) {
            asm volatile("fence.proxy.async.shared::cta;" ::: "memory");
            asm volatile("cp.async.bulk.global.shared::cta.bulk_group [%0], [%1], %2;"
                         :: "l"(orow + h), "r"(su32(srow4)), "r"(NV * 16) : "memory");
            asm volatile("cp.async.bulk.commit_group;" ::: "memory");
            asm volatile("cp.async.bulk.wait_group 0;" ::: "memory");
        }
    } else {
        // out row misaligned vs in row (not expected with cudaMalloc bases)
        for (int k = tid; k < 4 * NV; k += NT) orow[h + k] = srow[k];
    }
}

extern "C" void kernel_launch(void* const* d_in, const int* in_sizes, int n_in,
                              void* d_out, int out_size) {
    (void)n_in; (void)out_size;
    int Bn = in_sizes[0] / CDIM;
    rerank_kernel<<<Bn, NT>>>(
        (const float*)d_in[0],  (const float*)d_in[1],  (const float*)d_in[2],
        (const float*)d_in[3],  (const float*)d_in[4],  (const int*)d_in[5],
        (const int*)d_in[6],    (const int*)d_in[7],    (const float*)d_in[8],
        (const float*)d_in[9],  (const float*)d_in[10], (const float*)d_in[11],
        (const float*)d_in[12], (const float*)d_in[13], (float*)d_out);
}

// round 10
// speedup vs baseline: 1.6848x; 1.0383x over previous
#include <cuda_runtime.h>

#define CDIM 3755
#define NV 938              // (CDIM - h) >> 2 == 938 for every h in 0..3
#define RDIM 214
#define SDIM 13
#define SCBDIM 30
#define STDIM 6
#define HDIM 64
#define KTOP 20
#define CAP 512
#define NT 256
#define NEGF 3.4e38f
#define THR0 2.2f

__device__ __forceinline__ unsigned f2key(float x) {
    unsigned u = __float_as_uint(x);
    return (u & 0x80000000u) ? ~u : (u | 0x80000000u);
}
__device__ __forceinline__ float key2f(unsigned k) {
    return __uint_as_float((k & 0x80000000u) ? (k & 0x7FFFFFFFu) : ~k);
}
__device__ __forceinline__ unsigned long long packvi(float v, int j) {
    return ((unsigned long long)f2key(v) << 32) | (unsigned)(0x7FFFFFFF - j);
}
__device__ __forceinline__ unsigned su32(const void* p) {
    unsigned a;
    asm("{ .reg .u64 t; cvta.to.shared.u64 t, %1; cvt.u32.u64 %0, t; }" : "=r"(a) : "l"(p));
    return a;
}

__global__ void __launch_bounds__(NT) rerank_kernel(
    const float* __restrict__ charL, const float* __restrict__ radL,
    const float* __restrict__ structL, const float* __restrict__ scL,
    const float* __restrict__ styL, const int* __restrict__ rmask,
    const int* __restrict__ slab, const int* __restrict__ sclab,
    const float* __restrict__ sig, const float* __restrict__ W1,
    const float* __restrict__ b1, const float* __restrict__ W2,
    const float* __restrict__ b2, const float* __restrict__ rwp,
    float* __restrict__ out)
{
    __shared__ __align__(128) float4 srow4[NV];     // TMA-loaded middle of the row
    __shared__ float shHT[8];                        // head [0..3], tail [4..7]
    __shared__ __align__(8) unsigned long long s_mbar;
    __shared__ unsigned long long cpack[CAP];
    __shared__ float rps[RDIM];
    __shared__ float w1s[6 * HDIM], b1sh[HDIM], w2sh[HDIM];
    __shared__ float sprob[SDIM], predn[STDIM];
    __shared__ float feat6[KTOP][6];
    __shared__ int tIdx[KTOP];
    __shared__ float tVal[KTOP];
    __shared__ float reds[8], redt[8], redm[8];
    __shared__ unsigned long long red64[8];
    __shared__ unsigned long long s_prev;
    __shared__ float s_sum, s_shift, s_total, s_b2, s_rw;
    __shared__ int s_ncand, s_spred;

    float* srow = (float*)srow4;
    const int b = blockIdx.x;
    const int tid = threadIdx.x, lane = tid & 31, wid = tid >> 5;

    const float* row = charL + (size_t)b * CDIM;
    float* orow = out + (size_t)b * CDIM;
    const int h = (4 - (int)(((size_t)row >> 2) & 3)) & 3;
    const int tl = 3 - h;
    const int ho = (4 - (int)(((size_t)orow >> 2) & 3)) & 3;

    // ---- init: weights + mbarrier ----
    for (int i = tid; i < 6 * HDIM; i += NT) w1s[i] = W1[i];
    if (tid < HDIM) { b1sh[tid] = b1[tid]; w2sh[tid] = W2[tid]; }
    if (tid == 0) {
        s_b2 = b2[0]; s_rw = rwp[0]; s_ncand = 0; s_shift = 0.f;
        asm volatile("mbarrier.init.shared.b64 [%0], 1;" :: "r"(su32(&s_mbar)) : "memory");
    }
    __syncthreads();

    // ---- issue TMA bulk load of the aligned middle ----
    if (tid == 0) {
        unsigned mb = su32(&s_mbar);
        asm volatile("mbarrier.arrive.expect_tx.shared.b64 _, [%0], %1;"
                     :: "r"(mb), "r"(NV * 16) : "memory");
        asm volatile("cp.async.bulk.shared::cta.global.mbarrier::complete_tx::bytes "
                     "[%0], [%1], %2, [%3];"
                     :: "r"(su32(srow4)), "l"(row + h), "r"(NV * 16), "r"(mb) : "memory");
    }

    // ---- head/tail scalars: load + copy-out + stash in smem ----
    float seHT = 0.f;
    if (wid == 0 && lane < h) {
        float v = row[lane]; shHT[lane] = v; orow[lane] = v; seHT = __expf(v);
    }
    if (wid == 1 && lane < tl) {
        int j = h + 4 * NV + lane;
        float v = row[j]; shHT[4 + lane] = v; orow[j] = v; seHT = __expf(v);
    }

    // ---- radical sigmoid + total (overlaps TMA flight) ----
    float tp = 0.f;
    if (tid < RDIM) {
        float p = 1.f / (1.f + __expf(-radL[(size_t)b * RDIM + tid]));
        rps[tid] = p; tp = p;
    }
    // side tasks on distinct warps
    if (tid == 65) {
        const float* st = structL + (size_t)b * SDIM;
        float m = st[0]; float e[SDIM];
        for (int i = 1; i < SDIM; i++) m = fmaxf(m, st[i]);
        float s = 0.f;
        for (int i = 0; i < SDIM; i++) { e[i] = __expf(st[i] - m); s += e[i]; }
        float inv = 1.f / s;
        for (int i = 0; i < SDIM; i++) sprob[i] = e[i] * inv;
    }
    if (tid == 97) {
        const float* sc = scL + (size_t)b * SCBDIM;
        float m = sc[0]; int mi = 0;
        for (int i = 1; i < SCBDIM; i++) { float vv = sc[i]; if (vv > m) { m = vv; mi = i; } }
        s_spred = mi;
    }
    if (tid == 129) {
        const float* sy = styL + (size_t)b * STDIM;
        float vv[STDIM]; float n2 = 0.f;
        for (int i = 0; i < STDIM; i++) { vv[i] = sy[i]; n2 += vv[i] * vv[i]; }
        float n = fmaxf(sqrtf(n2), 1e-12f);
        for (int i = 0; i < STDIM; i++) predn[i] = vv[i] / n;
    }

    // ---- wait for TMA load completion ----
    {
        unsigned mb = su32(&s_mbar);
        unsigned done;
        do {
            asm volatile(
                "{\n\t.reg .pred p;\n\t"
                "mbarrier.try_wait.parity.shared.b64 p, [%1], 0;\n\t"
                "selp.b32 %0, 1, 0, p;\n\t}"
                : "=r"(done) : "r"(mb) : "memory");
        } while (!done);
    }

    // ---- fused sweep: unshifted expsum + order-free threshold collect ----
    float se = seHT;
    const float t0 = THR0;
    #pragma unroll
    for (int u = 0; u < 4; u++) {
        int i = tid + u * NT;
        float4 w;
        if (u < 3 || i < NV) {
            w = srow4[i];
            se += __expf(w.x) + __expf(w.y) + __expf(w.z) + __expf(w.w);
        } else { w.x = w.y = w.z = w.w = -NEGF; }
        int c = (w.x >= t0) + (w.y >= t0) + (w.z >= t0) + (w.w >= t0);
        if (c) {
            int pos = atomicAdd(&s_ncand, c);
            int j0 = h + 4 * i;
            if (w.x >= t0) { if (pos < CAP) cpack[pos] = packvi(w.x, j0); pos++; }
            if (w.y >= t0) { if (pos < CAP) cpack[pos] = packvi(w.y, j0 + 1); pos++; }
            if (w.z >= t0) { if (pos < CAP) cpack[pos] = packvi(w.z, j0 + 2); pos++; }
            if (w.w >= t0) { if (pos < CAP) cpack[pos] = packvi(w.w, j0 + 3); }
        }
    }
    // head/tail candidates
    if (wid == 0 && lane < h) {
        float v = shHT[lane];
        if (v >= t0) { int pos = atomicAdd(&s_ncand, 1); if (pos < CAP) cpack[pos] = packvi(v, lane); }
    }
    if (wid == 1 && lane < tl) {
        float v = shHT[4 + lane];
        if (v >= t0) { int pos = atomicAdd(&s_ncand, 1); if (pos < CAP) cpack[pos] = packvi(v, h + 4 * NV + lane); }
    }
    #pragma unroll
    for (int o = 16; o; o >>= 1) {
        se += __shfl_xor_sync(~0u, se, o);
        tp += __shfl_xor_sync(~0u, tp, o);
    }
    if (lane == 0) { reds[wid] = se; redt[wid] = tp; }
    __syncthreads();
    if (tid == 0) {
        float ss = 0.f, tt = 0.f;
        for (int w = 0; w < 8; w++) { ss += reds[w]; tt += redt[w]; }
        s_sum = ss; s_total = tt;
    }
    __syncthreads();

    // ---- guard: expsum overflow/underflow (never taken for sane logits) ----
    if (isinf(s_sum) || isnan(s_sum) || s_sum < 1e-30f) {
        float mx = -NEGF;
        for (int k = tid; k < 4 * NV; k += NT) mx = fmaxf(mx, srow[k]);
        if (tid < h) mx = fmaxf(mx, shHT[tid]);
        if (tid >= 32 && tid - 32 < tl) mx = fmaxf(mx, shHT[4 + tid - 32]);
        #pragma unroll
        for (int o = 16; o; o >>= 1) mx = fmaxf(mx, __shfl_xor_sync(~0u, mx, o));
        if (lane == 0) redm[wid] = mx;
        __syncthreads();
        if (tid == 0) {
            float m = redm[0];
            for (int w = 1; w < 8; w++) m = fmaxf(m, redm[w]);
            s_shift = m;
        }
        __syncthreads();
        const float shv = s_shift;
        float se2 = 0.f;
        for (int k = tid; k < 4 * NV; k += NT) se2 += __expf(srow[k] - shv);
        if (tid < h) se2 += __expf(shHT[tid] - shv);
        if (tid >= 32 && tid - 32 < tl) se2 += __expf(shHT[4 + tid - 32] - shv);
        #pragma unroll
        for (int o = 16; o; o >>= 1) se2 += __shfl_xor_sync(~0u, se2, o);
        if (lane == 0) reds[wid] = se2;
        __syncthreads();
        if (tid == 0) { float ss = 0.f; for (int w = 0; w < 8; w++) ss += reds[w]; s_sum = ss; }
        __syncthreads();
    }

    // ---- retry with lower threshold (rare) ----
    int nc = s_ncand;
    float t = t0;
    while (nc < KTOP) {
        __syncthreads();
        if (tid == 0) s_ncand = 0;
        t -= 1.5f;
        __syncthreads();
        for (int base_k = 0; base_k < 4 * NV; base_k += NT) {
            int k = base_k + tid;
            float v = (k < 4 * NV) ? srow[k] : -NEGF;
            if (v >= t) {
                int pos = atomicAdd(&s_ncand, 1);
                if (pos < CAP) cpack[pos] = packvi(v, h + k);
            }
        }
        if (wid == 0 && lane < h) {
            float v = shHT[lane];
            if (v >= t) { int pos = atomicAdd(&s_ncand, 1); if (pos < CAP) cpack[pos] = packvi(v, lane); }
        }
        if (wid == 1 && lane < tl) {
            float v = shHT[4 + lane];
            if (v >= t) { int pos = atomicAdd(&s_ncand, 1); if (pos < CAP) cpack[pos] = packvi(v, h + 4 * NV + lane); }
        }
        __syncthreads();
        nc = s_ncand;
    }

    // ---- selection: parallel rank (ties: lower index wins, encoded in pack) ----
    if (nc <= NT) {
        if (tid - lane < nc) {
            unsigned long long p0 = (tid < nc) ? cpack[tid] : 0ull;
            int r0 = 0;
            #pragma unroll 4
            for (int j = 0; j < nc; j++) r0 += (cpack[j] > p0);
            if (tid < nc && r0 < KTOP) {
                tIdx[r0] = 0x7FFFFFFF - (int)(p0 & 0xFFFFFFFFu);
                tVal[r0] = key2f((unsigned)(p0 >> 32));
            }
        }
    } else if (nc <= CAP) {
        unsigned long long p0 = cpack[tid];
        unsigned long long p1 = (tid + NT < nc) ? cpack[tid + NT] : 0ull;
        int r0 = 0, r1 = 0;
        for (int j = 0; j < nc; j++) {
            unsigned long long q = cpack[j];
            r0 += (q > p0); r1 += (q > p1);
        }
        if (r0 < KTOP) {
            tIdx[r0] = 0x7FFFFFFF - (int)(p0 & 0xFFFFFFFFu);
            tVal[r0] = key2f((unsigned)(p0 >> 32));
        }
        if (tid + NT < nc && r1 < KTOP) {
            tIdx[r1] = 0x7FFFFFFF - (int)(p1 & 0xFFFFFFFFu);
            tVal[r1] = key2f((unsigned)(p1 >> 32));
        }
    } else {
        // robust fallback (adversarial only): 20 rounds of block argmax over smem
        unsigned long long prev = ~0ull;
        for (int k = 0; k < KTOP; k++) {
            unsigned long long best = 0ull;
            for (int kk = tid; kk < 4 * NV; kk += NT) {
                unsigned long long p = packvi(srow[kk], h + kk);
                if (p < prev && p > best) best = p;
            }
            if (tid < h) { unsigned long long p = packvi(shHT[tid], tid); if (p < prev && p > best) best = p; }
            if (tid >= 32 && tid - 32 < tl) {
                unsigned long long p = packvi(shHT[4 + tid - 32], h + 4 * NV + tid - 32);
                if (p < prev && p > best) best = p;
            }
            #pragma unroll
            for (int o = 16; o; o >>= 1) {
                unsigned long long q = __shfl_xor_sync(~0u, best, o);
                if (q > best) best = q;
            }
            if (lane == 0) red64[wid] = best;
            __syncthreads();
            if (tid == 0) {
                unsigned long long m = red64[0];
                for (int w = 1; w < 8; w++) if (red64[w] > m) m = red64[w];
                tIdx[k] = 0x7FFFFFFF - (int)(m & 0xFFFFFFFFu);
                tVal[k] = key2f((unsigned)(m >> 32));
                s_prev = m;
            }
            __syncthreads();
            prev = s_prev;
        }
    }
    __syncthreads();

    // ---- features: 8-lane groups for radical dot; threads 160.. do scalars ----
    const int g = tid >> 3, gl = tid & 7;
    const float total = s_total;
    if (g < KTOP) {
        int c = tIdx[g];
        const int2* m2 = (const int2*)(rmask + (size_t)c * RDIM);
        float det = 0.f; int cnt = 0;
        for (int r = gl; r < RDIM / 2; r += 8) {
            int2 mm = m2[r];
            det = fmaf((float)mm.x, rps[2 * r], det);
            det = fmaf((float)mm.y, rps[2 * r + 1], det);
            cnt += mm.x + mm.y;
        }
        #pragma unroll
        for (int o = 4; o; o >>= 1) {
            det += __shfl_xor_sync(~0u, det, o);
            cnt += __shfl_xor_sync(~0u, cnt, o);
        }
        if (gl == 0) {
            feat6[g][0] = det / fmaxf((float)cnt, 1.f);
            feat6[g][1] = (total - det) / fmaxf(total, 1e-6f);
        }
    }
    if (tid >= 160 && tid < 160 + KTOP) {
        int k = tid - 160;
        int c = tIdx[k];
        feat6[k][2] = sprob[slab[c]];
        feat6[k][3] = fabsf((float)(s_spred - sclab[c])) * (1.f / 29.f);
        const float* s6 = sig + (size_t)c * STDIM;
        float n2 = 0.f, dd = 0.f;
        #pragma unroll
        for (int i = 0; i < STDIM; i++) {
            float vv = s6[i];
            n2 += vv * vv;
            dd += predn[i] * vv;
        }
        float nrm = sqrtf(n2);
        feat6[k][4] = (nrm > 1e-6f) ? dd / fmaxf(nrm, 1e-12f) : 0.f;
        feat6[k][5] = __expf(tVal[k] - s_shift) / s_sum;
    }
    __syncthreads();

    // ---- MLP 6->64->1; patch scores into smem row (or global for head/tail) ----
    if (g < KTOP) {
        float f0 = feat6[g][0], f1 = feat6[g][1], f2 = feat6[g][2];
        float f3 = feat6[g][3], f4 = feat6[g][4], f5 = feat6[g][5];
        float score = 0.f;
        #pragma unroll
        for (int u = 0; u < 8; u++) {
            int j = gl + u * 8;
            float hh = b1sh[j] + f0 * w1s[j] + f1 * w1s[HDIM + j]
                     + f2 * w1s[2 * HDIM + j] + f3 * w1s[3 * HDIM + j]
                     + f4 * w1s[4 * HDIM + j] + f5 * w1s[5 * HDIM + j];
            score += fmaxf(hh, 0.f) * w2sh[j];
        }
        #pragma unroll
        for (int o = 4; o; o >>= 1) score += __shfl_xor_sync(~0u, score, o);
        if (gl == 0) {
            int idx = tIdx[g];
            float comb = tVal[g] + s_rw * (score + s_b2);
            if (idx >= h && idx < h + 4 * NV) srow[idx - h] = comb;
            else orow[idx] = comb;       // head/tail patch (ordered after copy by barriers)
        }
    }
    __syncthreads();

    // ---- write the middle back: TMA bulk store (or scalar fallback) ----
    if (ho == h) {
        if (tid == 0) {
            asm volatile("fence.proxy.async.shared::cta;" ::: "memory");
            asm volatile("cp.async.bulk.global.shared::cta.bulk_group [%0], [%1], %2;"
                         :: "l"(orow + h), "r"(su32(srow4)), "r"(NV * 16) : "memory");
            asm volatile("cp.async.bulk.commit_group;" ::: "memory");
            asm volatile("cp.async.bulk.wait_group 0;" ::: "memory");
        }
    } else {
        // out row misaligned vs in row (not expected with cudaMalloc bases)
        for (int k = tid; k < 4 * NV; k += NT) orow[h + k] = srow[k];
    }
}

extern "C" void kernel_launch(void* const* d_in, const int* in_sizes, int n_in,
                              void* d_out, int out_size) {
    (void)n_in; (void)out_size;
    int Bn = in_sizes[0] / CDIM;
    rerank_kernel<<<Bn, NT>>>(
        (const float*)d_in[0],  (const float*)d_in[1],  (const float*)d_in[2],
        (const float*)d_in[3],  (const float*)d_in[4],  (const int*)d_in[5],
        (const int*)d_in[6],    (const int*)d_in[7],    (const float*)d_in[8],
        (const float*)d_in[9],  (const float*)d_in[10], (const float*)d_in[11],
        (const float*)d_in[12], (const float*)d_in[13], (float*)d_out);
}